// round 8
// baseline (speedup 1.0000x reference)
#include <cuda_runtime.h>
#include <cstdint>
#include <float.h>

// SpatialAttention2D fused: out[b,c] = sum_hw x[b,c,hw] * softmax_hw(sum_c x*w + bias)
// bias softmax-invariant -> never read.
//
// Pass1: grid = 64*16 = 1024 CTAs, 512 thr, 2 CTAs/SM (regs<=64, smem ~101KB).
//   CTA (b,g) owns 64 hw positions, 8 chunks of 8. Tiles (1024ch x 8hw = 32KB)
//   stream GMEM->SMEM via cp.async.cg into a 3-deep ring (issue c+2 at iter c).
//   Per chunk: scores (col=tid&7, 16 rows/thread, 2-shfl reduce) -> partials
//   (double-buffered) -> ONE bar -> all-warp redundant online-softmax ->
//   phase B (rows tid, tid+512 from smem; acc = acc*scale + dot(x, p)).
//   Only 2 __syncthreads per chunk; buffer reuse protected by next iter's bar1.
// Pass2: log-sum-exp merge of 16 partials per batch.

#define BATCH    64
#define CCH      1024
#define HWN      1024
#define GSPLIT   16
#define S_CTA    (HWN / GSPLIT)   // 64
#define S2       8
#define NSUB     (S_CTA / S2)     // 8
#define NTHREADS 512
#define ROWF     8                // floats per tile row (8 hw positions)
#define TILEF    (CCH * ROWF)     // 8192 floats per tile buffer

// smem layout (floats)
#define OFF_SW    0
#define OFF_TILE  (OFF_SW + CCH)              // 1024
#define OFF_PART  (OFF_TILE + 3 * TILEF)      // 1024 + 24576
#define SMEM_FLOATS (OFF_PART + 2 * 128 + 16)
#define SMEM_BYTES  (SMEM_FLOATS * 4)         // ~103.5 KB

__device__ float  g_acc[BATCH * GSPLIT * CCH];   // 4 MB scratch
__device__ float2 g_mz[BATCH * GSPLIT];

__device__ __forceinline__ void cp16(uint32_t dst, const float* src) {
    asm volatile("cp.async.cg.shared.global [%0], [%1], 16;" :: "r"(dst), "l"(src));
}

__global__ __launch_bounds__(NTHREADS, 2)
void spatial_attn2d_pass1(const float* __restrict__ x,
                          const float* __restrict__ w)
{
    extern __shared__ float sm[];
    float* s_w  = sm + OFF_SW;
    float* part = sm + OFF_PART;

    const int tid  = threadIdx.x;
    const int lane = tid & 31;
    const int wid  = tid >> 5;
    const int b    = blockIdx.x >> 4;
    const int g    = blockIdx.x & 15;
    const int hw0  = g * S_CTA;

    s_w[tid]       = w[tid];
    s_w[tid + 512] = w[tid + 512];

    const float* xb = x + (size_t)b * CCH * HWN;

    // cp.async mapping: thread covers rows {R, R+256, R+512, R+768}, half h (16B)
    const int R = tid >> 1;
    const int h = tid & 1;
    const float* gsrc = xb + (size_t)R * HWN + hw0 + h * 4;
    const uint32_t sdst = (uint32_t)__cvta_generic_to_shared(sm + OFF_TILE)
                        + (uint32_t)(R * ROWF + h * 4) * 4;

    // score mapping: col j, rows rgrp + 64k
    const int j    = tid & 7;
    const int rgrp = tid >> 3;

    __syncthreads();   // s_w visible before first score phase

    // issue chunk c into ring buffer c%3
    #define ISSUE(c) do {                                              \
        uint32_t _d = sdst + (uint32_t)((c) % 3) * (TILEF * 4);        \
        const float* _s = gsrc + (c) * S2;                             \
        cp16(_d,                    _s);                               \
        cp16(_d + 256 * ROWF * 4,   _s + 256 * HWN);                   \
        cp16(_d + 512 * ROWF * 4,   _s + 512 * HWN);                   \
        cp16(_d + 768 * ROWF * 4,   _s + 768 * HWN);                   \
        asm volatile("cp.async.commit_group;");                        \
    } while (0)

    ISSUE(0);
    ISSUE(1);

    float m_run = -FLT_MAX, Z = 0.0f;
    float acc0 = 0.0f, acc1 = 0.0f;

    #pragma unroll
    for (int c = 0; c < NSUB; c++) {
        if (c == NSUB - 1) asm volatile("cp.async.wait_group 0;");
        else               asm volatile("cp.async.wait_group 1;");
        __syncthreads();                 // bar1: tile c ready; buf (c+2)%3 free
        if (c + 2 < NSUB) ISSUE(c + 2);  // 2-chunk lookahead

        const float* tile = sm + OFF_TILE + (c % 3) * TILEF;

        // ---- scores: this thread's col j over 16 rows ----
        float ps = 0.0f;
        #pragma unroll
        for (int k = 0; k < 16; k++)
            ps = fmaf(tile[(rgrp + 64 * k) * ROWF + j], s_w[rgrp + 64 * k], ps);
        ps += __shfl_xor_sync(0xffffffffu, ps, 8);
        ps += __shfl_xor_sync(0xffffffffu, ps, 16);
        float* pb = part + (c & 1) * 128;
        if (lane < 8) pb[wid * 8 + lane] = ps;
        __syncthreads();                 // bar2: partials visible

        // ---- redundant online softmax in every warp (identical values) ----
        float s = 0.0f;
        #pragma unroll
        for (int ww = 0; ww < 16; ww++) s += pb[ww * 8 + j];
        float ml = s;
        ml = fmaxf(ml, __shfl_xor_sync(0xffffffffu, ml, 1));
        ml = fmaxf(ml, __shfl_xor_sync(0xffffffffu, ml, 2));
        ml = fmaxf(ml, __shfl_xor_sync(0xffffffffu, ml, 4));
        float m_new = fmaxf(m_run, ml);
        float scale = __expf(m_run - m_new);
        float p = __expf(s - m_new);
        float zc = p;
        zc += __shfl_xor_sync(0xffffffffu, zc, 1);
        zc += __shfl_xor_sync(0xffffffffu, zc, 2);
        zc += __shfl_xor_sync(0xffffffffu, zc, 4);
        Z = fmaf(Z, scale, zc);
        m_run = m_new;

        // distribute p[0..7] within each 8-lane group
        const int b8 = lane & ~7;
        float p0 = __shfl_sync(0xffffffffu, p, b8 + 0);
        float p1 = __shfl_sync(0xffffffffu, p, b8 + 1);
        float p2 = __shfl_sync(0xffffffffu, p, b8 + 2);
        float p3 = __shfl_sync(0xffffffffu, p, b8 + 3);
        float p4 = __shfl_sync(0xffffffffu, p, b8 + 4);
        float p5 = __shfl_sync(0xffffffffu, p, b8 + 5);
        float p6 = __shfl_sync(0xffffffffu, p, b8 + 6);
        float p7 = __shfl_sync(0xffffffffu, p, b8 + 7);

        // ---- phase B: rows tid and tid+512 from smem ----
        {
            float4 v0 = *(const float4*)(tile + tid * ROWF);
            float4 v1 = *(const float4*)(tile + tid * ROWF + 4);
            float d0 = v0.x * p0 + v0.y * p1 + v0.z * p2 + v0.w * p3
                     + v1.x * p4 + v1.y * p5 + v1.z * p6 + v1.w * p7;
            acc0 = fmaf(acc0, scale, d0);
            float4 u0 = *(const float4*)(tile + (tid + 512) * ROWF);
            float4 u1 = *(const float4*)(tile + (tid + 512) * ROWF + 4);
            float d1 = u0.x * p0 + u0.y * p1 + u0.z * p2 + u0.w * p3
                     + u1.x * p4 + u1.y * p5 + u1.z * p6 + u1.w * p7;
            acc1 = fmaf(acc1, scale, d1);
        }
        // no barrier here: buffer reuse is protected by next iteration's bar1,
        // partials double-buffer is protected by bar1(c+1)+bar1(c+2) chain.
    }

    const int slot = blockIdx.x;
    g_acc[(size_t)slot * CCH + tid]       = acc0;   // channel tid
    g_acc[(size_t)slot * CCH + tid + 512] = acc1;   // channel tid+512
    if (tid == 0) g_mz[slot] = make_float2(m_run, Z);
    #undef ISSUE
}

__global__ __launch_bounds__(512, 1)
void spatial_attn2d_pass2(float* __restrict__ out)
{
    const int b = blockIdx.x >> 1;
    const int c = (blockIdx.x & 1) * 512 + threadIdx.x;

    float m[GSPLIT], z[GSPLIT];
    float M = -FLT_MAX;
    #pragma unroll
    for (int i = 0; i < GSPLIT; i++) {
        float2 mz = g_mz[b * GSPLIT + i];
        m[i] = mz.x; z[i] = mz.y;
        M = fmaxf(M, m[i]);
    }
    float den = 0.0f, num = 0.0f;
    #pragma unroll
    for (int i = 0; i < GSPLIT; i++) {
        float e = __expf(m[i] - M);
        den = fmaf(z[i], e, den);
        num = fmaf(g_acc[(size_t)(b * GSPLIT + i) * CCH + c], e, num);
    }
    out[(size_t)b * CCH + c] = num / den;
}

extern "C" void kernel_launch(void* const* d_in, const int* in_sizes, int n_in,
                              void* d_out, int out_size)
{
    const float* x = (const float*)d_in[0];   // [64,1024,32,32]
    const float* w = (const float*)d_in[1];   // [1024]
    // d_in[2] = attn_b : softmax-invariant, unused
    float* out = (float*)d_out;               // [64,1024]

    cudaFuncSetAttribute(spatial_attn2d_pass1,
                         cudaFuncAttributeMaxDynamicSharedMemorySize, SMEM_BYTES);
    spatial_attn2d_pass1<<<BATCH * GSPLIT, NTHREADS, SMEM_BYTES>>>(x, w);
    spatial_attn2d_pass2<<<BATCH * 2, 512>>>(out);
}

// round 10
// speedup vs baseline: 1.5117x; 1.5117x over previous
#include <cuda_runtime.h>
#include <float.h>

// SpatialAttention2D fused, cache-resident two-phase version.
// out[b,c] = sum_hw x[b,c,hw] * softmax_hw(sum_c x[b,c,hw]*w[c] + bias)
// bias softmax-invariant -> never read.
//
// Pass1: grid = 64*16 = 1024 CTAs (b, g), 512 threads, ~2-3 CTAs/SM (smem 17KB).
//   CTA slice: all 1024 channels x 64 hw columns (256 KB).
//   Thread (rg = tid>>4, q = tid&15) owns col-piece [q*4, q*4+4) of rows rg+32k.
//   Warp per iteration reads 2 rows x 256 B dense -> 4 fully-used 128B lines/LDG
//   (optimal L1tex wavefronts; this was the hidden cost of all prior versions).
//   Phase A: barrier-free streaming score accumulation (32 LDG/thread, deep MLP).
//   One softmax (warp 0) over the 64 slice scores. 3 CTA-wide barriers TOTAL.
//   Phase B: re-read slice in REVERSE row order -> newest lines hit L1, rest L2
//   (chip reads during one CTA lifetime ~77MB < 126MB L2 -> no DRAM re-read).
//   Per row: dot with p, 4-shfl reduce over the 16 col-pieces, stage, store.
// Pass2: log-sum-exp merge of the 16 slice partials per batch.

#define BATCH    64
#define CCH      1024
#define HWN      1024
#define GSPLIT   16
#define SCOLS    64          // hw columns per CTA slice
#define NTHREADS 512

__device__ float  g_acc[BATCH * GSPLIT * CCH];   // 4 MB scratch
__device__ float2 g_mz[BATCH * GSPLIT];

struct SMem {
    float w[CCH];            // 4 KB  channel weights
    float part[32 * SCOLS];  // 8 KB  score partials, part[rg*64 + col]
    float p[SCOLS];          // 256 B exp(s - m)
    float outbuf[CCH];       // 4 KB  staging for coalesced scratch store
};

__global__ __launch_bounds__(NTHREADS, 2)
void spatial_attn2d_pass1(const float* __restrict__ x,
                          const float* __restrict__ w)
{
    __shared__ SMem sm;

    const int tid  = threadIdx.x;
    const int lane = tid & 31;
    const int wid  = tid >> 5;
    const int b    = blockIdx.x >> 4;
    const int g    = blockIdx.x & 15;

    const int q  = tid & 15;     // col piece: cols [q*4, q*4+4)
    const int rg = tid >> 4;     // row residue: rows rg + 32k, k = 0..31

    sm.w[tid]       = w[tid];
    sm.w[tid + 512] = w[tid + 512];

    // thread base: batch b, col offset g*64 + q*4, row handled via k
    const float* base = x + (size_t)b * CCH * HWN + g * SCOLS + q * 4
                          + (size_t)rg * HWN;

    __syncthreads();   // bar0: weights visible

    // ---------------- Phase A: streaming score partials (no syncs) ----------
    float4 ps = make_float4(0.f, 0.f, 0.f, 0.f);
    #pragma unroll 8
    for (int k = 0; k < 32; k++) {
        float4 v = *(const float4*)(base + (size_t)(32 * k) * HWN);
        float wc = sm.w[rg + 32 * k];           // 2-way broadcast LDS
        ps.x = fmaf(v.x, wc, ps.x);
        ps.y = fmaf(v.y, wc, ps.y);
        ps.z = fmaf(v.z, wc, ps.z);
        ps.w = fmaf(v.w, wc, ps.w);
    }
    *(float4*)&sm.part[rg * SCOLS + q * 4] = ps;
    __syncthreads();   // bar1: partials visible

    // ---------------- Softmax over the 64 slice scores (warp 0) -------------
    if (wid == 0) {
        float s0 = 0.f, s1 = 0.f;
        #pragma unroll 8
        for (int r = 0; r < 32; r++) {
            s0 += sm.part[r * SCOLS + lane];        // conflict-free
            s1 += sm.part[r * SCOLS + lane + 32];
        }
        float m = fmaxf(s0, s1);
        #pragma unroll
        for (int o = 16; o; o >>= 1)
            m = fmaxf(m, __shfl_xor_sync(0xffffffffu, m, o));
        float p0 = __expf(s0 - m);
        float p1 = __expf(s1 - m);
        float z = p0 + p1;
        #pragma unroll
        for (int o = 16; o; o >>= 1)
            z += __shfl_xor_sync(0xffffffffu, z, o);
        sm.p[lane]      = p0;
        sm.p[lane + 32] = p1;
        if (lane == 0) g_mz[blockIdx.x] = make_float2(m, z);
    }
    __syncthreads();   // bar2: p visible

    // ---------------- Phase B: weighted sum, reverse order (L1/L2 hits) -----
    const float4 pq = *(const float4*)&sm.p[q * 4];   // fixed per thread
    #pragma unroll 8
    for (int kk = 0; kk < 32; kk++) {
        const int k = 31 - kk;                        // newest lines first
        float4 v = *(const float4*)(base + (size_t)(32 * k) * HWN);
        float d = v.x * pq.x + v.y * pq.y + v.z * pq.z + v.w * pq.w;
        // reduce over the 16 col-pieces (lane bits 0..3)
        d += __shfl_xor_sync(0xffffffffu, d, 1);
        d += __shfl_xor_sync(0xffffffffu, d, 2);
        d += __shfl_xor_sync(0xffffffffu, d, 4);
        d += __shfl_xor_sync(0xffffffffu, d, 8);
        if (q == 0) sm.outbuf[rg + 32 * k] = d;       // lanes 0,16
    }
    __syncthreads();   // bar3: outbuf complete

    const int slot = blockIdx.x;
    g_acc[(size_t)slot * CCH + tid]       = sm.outbuf[tid];
    g_acc[(size_t)slot * CCH + tid + 512] = sm.outbuf[tid + 512];
}

__global__ __launch_bounds__(128, 8)
void spatial_attn2d_pass2(float* __restrict__ out)
{
    const int b = blockIdx.x >> 3;
    const int c = (blockIdx.x & 7) * 128 + threadIdx.x;

    float m[GSPLIT], z[GSPLIT];
    float M = -FLT_MAX;
    #pragma unroll
    for (int i = 0; i < GSPLIT; i++) {
        float2 mz = g_mz[b * GSPLIT + i];
        m[i] = mz.x; z[i] = mz.y;
        M = fmaxf(M, m[i]);
    }
    float den = 0.0f, num = 0.0f;
    #pragma unroll
    for (int i = 0; i < GSPLIT; i++) {
        float e = __expf(m[i] - M);
        den = fmaf(z[i], e, den);
        num = fmaf(g_acc[(size_t)(b * GSPLIT + i) * CCH + c], e, num);
    }
    out[(size_t)b * CCH + c] = num / den;
}

extern "C" void kernel_launch(void* const* d_in, const int* in_sizes, int n_in,
                              void* d_out, int out_size)
{
    const float* x = (const float*)d_in[0];   // [64,1024,32,32]
    const float* w = (const float*)d_in[1];   // [1024]
    // d_in[2] = attn_b : softmax-invariant, unused
    float* out = (float*)d_out;               // [64,1024]

    spatial_attn2d_pass1<<<BATCH * GSPLIT, NTHREADS>>>(x, w);
    spatial_attn2d_pass2<<<BATCH * 8, 128>>>(out);
}